// round 1
// baseline (speedup 1.0000x reference)
#include <cuda_runtime.h>
#include <math.h>

#define CIN   128
#define COUT  128
#define NWARPS 16
#define NTHREADS (NWARPS * 32)

// Scratch for h after stage 2 (needed for the irregular parent gather).
// 64*4096 rows * 128 feats * 4B = 128 MiB, static device global (no allocation).
__device__ float g_H[64u * 4096u * 128u];

__device__ __forceinline__ float warp_sum(float v) {
#pragma unroll
    for (int o = 16; o; o >>= 1) v += __shfl_xor_sync(0xffffffffu, v, o);
    return v;
}

__device__ __forceinline__ float warp_max(float v) {
#pragma unroll
    for (int o = 16; o; o >>= 1) v = fmaxf(v, __shfl_xor_sync(0xffffffffu, v, o));
    return v;
}

__device__ __forceinline__ float elu1(float v) {
    return v > 0.0f ? v : expm1f(v);
}

// ---------------------------------------------------------------------------
// Kernel 1: h = elu(LN(elu(LN(x@W1 + b1)) @ W2 + b2))   -> g_H
// One warp per row. W1 and W2 live in shared memory for the whole block.
// Each lane owns 4 contiguous output columns (j = 4*lane + c) -> float4 smem
// loads of W rows are bank-conflict-free.
// ---------------------------------------------------------------------------
__global__ __launch_bounds__(NTHREADS, 1)
void k_mlp(const float* __restrict__ x,
           const float* __restrict__ W1, const float* __restrict__ b1,
           const float* __restrict__ g1, const float* __restrict__ be1,
           const float* __restrict__ W2, const float* __restrict__ b2,
           const float* __restrict__ g2, const float* __restrict__ be2,
           int nrows)
{
    extern __shared__ float sm[];
    float* W1s = sm;                    // 128*128
    float* W2s = sm + 16384;            // 128*128
    float* xb  = sm + 32768;            // NWARPS*128
    float* hb  = xb + NWARPS * 128;     // NWARPS*128

    const int tid = threadIdx.x;
    for (int i = tid; i < 4096; i += NTHREADS) {
        ((float4*)W1s)[i] = ((const float4*)W1)[i];
        ((float4*)W2s)[i] = ((const float4*)W2)[i];
    }
    __syncthreads();

    const int warp = tid >> 5, lane = tid & 31;
    float* xr = xb + warp * 128;
    float* hr = hb + warp * 128;

    const float4 b1v  = ((const float4*)b1)[lane];
    const float4 g1v  = ((const float4*)g1)[lane];
    const float4 be1v = ((const float4*)be1)[lane];
    const float4 b2v  = ((const float4*)b2)[lane];
    const float4 g2v  = ((const float4*)g2)[lane];
    const float4 be2v = ((const float4*)be2)[lane];

    for (long row = (long)blockIdx.x * NWARPS + warp; row < nrows;
         row += (long)gridDim.x * NWARPS) {
        // 1. stage-1 input row -> smem
        ((float4*)xr)[lane] = ((const float4*)(x + row * CIN))[lane];
        __syncwarp();

        // 2. GEMM1
        float a0 = b1v.x, a1 = b1v.y, a2 = b1v.z, a3 = b1v.w;
#pragma unroll 16
        for (int k = 0; k < CIN; k++) {
            const float xk = xr[k];
            const float4 w = ((const float4*)(W1s + k * COUT))[lane];
            a0 = fmaf(xk, w.x, a0);
            a1 = fmaf(xk, w.y, a1);
            a2 = fmaf(xk, w.z, a2);
            a3 = fmaf(xk, w.w, a3);
        }
        // LN1 + ELU
        float mu = warp_sum(a0 + a1 + a2 + a3) * (1.0f / COUT);
        a0 -= mu; a1 -= mu; a2 -= mu; a3 -= mu;
        float var = warp_sum(a0 * a0 + a1 * a1 + a2 * a2 + a3 * a3) * (1.0f / COUT);
        float rs = rsqrtf(var + 1e-5f);
        float4 h;
        h.x = elu1(a0 * rs * g1v.x + be1v.x);
        h.y = elu1(a1 * rs * g1v.y + be1v.y);
        h.z = elu1(a2 * rs * g1v.z + be1v.z);
        h.w = elu1(a3 * rs * g1v.w + be1v.w);

        ((float4*)hr)[lane] = h;
        __syncwarp();

        // 3. GEMM2
        float c0 = b2v.x, c1 = b2v.y, c2 = b2v.z, c3 = b2v.w;
#pragma unroll 16
        for (int k = 0; k < COUT; k++) {
            const float hk = hr[k];
            const float4 w = ((const float4*)(W2s + k * COUT))[lane];
            c0 = fmaf(hk, w.x, c0);
            c1 = fmaf(hk, w.y, c1);
            c2 = fmaf(hk, w.z, c2);
            c3 = fmaf(hk, w.w, c3);
        }
        // LN2 + ELU
        mu = warp_sum(c0 + c1 + c2 + c3) * (1.0f / COUT);
        c0 -= mu; c1 -= mu; c2 -= mu; c3 -= mu;
        var = warp_sum(c0 * c0 + c1 * c1 + c2 * c2 + c3 * c3) * (1.0f / COUT);
        rs = rsqrtf(var + 1e-5f);
        float4 o;
        o.x = elu1(c0 * rs * g2v.x + be2v.x);
        o.y = elu1(c1 * rs * g2v.y + be2v.y);
        o.z = elu1(c2 * rs * g2v.z + be2v.z);
        o.w = elu1(c3 * rs * g2v.w + be2v.w);
        ((float4*)(g_H + row * COUT))[lane] = o;
    }
}

// ---------------------------------------------------------------------------
// Kernel 2: per edge i: e = max(h[child], h[parent]);
//           r = elu(LN(e@Wr1 + br1)) @ Wr2 + br2  -> out[i]  (pre-logsumexp)
// ---------------------------------------------------------------------------
__global__ __launch_bounds__(NTHREADS, 1)
void k_edge(const int* __restrict__ pidx,
            const float* __restrict__ Wr1, const float* __restrict__ br1,
            const float* __restrict__ gr1, const float* __restrict__ ber1,
            const float* __restrict__ Wr2, const float* __restrict__ br2,
            float* __restrict__ out, int nedges, int Nm1, int N)
{
    extern __shared__ float sm[];
    float* Ws  = sm;            // 128*128
    float* w2s = sm + 16384;    // 128
    float* eb  = w2s + 128;     // NWARPS*128

    const int tid = threadIdx.x;
    for (int i = tid; i < 4096; i += NTHREADS)
        ((float4*)Ws)[i] = ((const float4*)Wr1)[i];
    if (tid < 32) ((float4*)w2s)[tid] = ((const float4*)Wr2)[tid];
    __syncthreads();

    const int warp = tid >> 5, lane = tid & 31;
    float* er = eb + warp * 128;

    const float4 bv  = ((const float4*)br1)[lane];
    const float4 gv  = ((const float4*)gr1)[lane];
    const float4 bev = ((const float4*)ber1)[lane];
    const float4 w2v = ((const float4*)w2s)[lane];
    const float br2v = br2[0];

    for (long i = (long)blockIdx.x * NWARPS + warp; i < nedges;
         i += (long)gridDim.x * NWARPS) {
        const int b = (int)(i / Nm1);
        const int n = (int)(i - (long)b * Nm1);
        const long crow = (long)b * N + n;
        const long prow = (long)pidx[i];

        const float4 c4 = ((const float4*)(g_H + crow * COUT))[lane];
        const float4 p4 = ((const float4*)(g_H + prow * COUT))[lane];
        float4 e4;
        e4.x = fmaxf(c4.x, p4.x);
        e4.y = fmaxf(c4.y, p4.y);
        e4.z = fmaxf(c4.z, p4.z);
        e4.w = fmaxf(c4.w, p4.w);

        __syncwarp();           // prior-iteration reads of er are done
        ((float4*)er)[lane] = e4;
        __syncwarp();

        float a0 = bv.x, a1 = bv.y, a2 = bv.z, a3 = bv.w;
#pragma unroll 16
        for (int k = 0; k < COUT; k++) {
            const float ek = er[k];
            const float4 w = ((const float4*)(Ws + k * COUT))[lane];
            a0 = fmaf(ek, w.x, a0);
            a1 = fmaf(ek, w.y, a1);
            a2 = fmaf(ek, w.z, a2);
            a3 = fmaf(ek, w.w, a3);
        }
        float mu = warp_sum(a0 + a1 + a2 + a3) * (1.0f / COUT);
        a0 -= mu; a1 -= mu; a2 -= mu; a3 -= mu;
        float var = warp_sum(a0 * a0 + a1 * a1 + a2 * a2 + a3 * a3) * (1.0f / COUT);
        const float rs = rsqrtf(var + 1e-5f);

        const float y0 = elu1(a0 * rs * gv.x + bev.x);
        const float y1 = elu1(a1 * rs * gv.y + bev.y);
        const float y2 = elu1(a2 * rs * gv.z + bev.z);
        const float y3 = elu1(a3 * rs * gv.w + bev.w);

        const float r = warp_sum(fmaf(y0, w2v.x,
                                 fmaf(y1, w2v.y,
                                 fmaf(y2, w2v.z, y3 * w2v.w))));
        if (lane == 0) out[i] = r + br2v;
    }
}

// ---------------------------------------------------------------------------
// Kernel 3: per batch row, out -= logsumexp(out)
// ---------------------------------------------------------------------------
__global__ __launch_bounds__(256)
void k_lse(float* __restrict__ out, int Nm1)
{
    __shared__ float red[8];
    __shared__ float bc;
    const int b = blockIdx.x;
    float* row = out + (long)b * Nm1;
    const int tid = threadIdx.x;

    float m = -3.4e38f;
    for (int i = tid; i < Nm1; i += 256) m = fmaxf(m, row[i]);
    m = warp_max(m);
    if ((tid & 31) == 0) red[tid >> 5] = m;
    __syncthreads();
    if (tid < 32) {
        float v = (tid < 8) ? red[tid] : -3.4e38f;
        v = warp_max(v);
        if (tid == 0) bc = v;
    }
    __syncthreads();
    const float M = bc;

    float s = 0.0f;
    for (int i = tid; i < Nm1; i += 256) s += expf(row[i] - M);
    s = warp_sum(s);
    __syncthreads();
    if ((tid & 31) == 0) red[tid >> 5] = s;
    __syncthreads();
    if (tid < 32) {
        float v = (tid < 8) ? red[tid] : 0.0f;
        v = warp_sum(v);
        if (tid == 0) bc = M + logf(v);
    }
    __syncthreads();
    const float lse = bc;
    for (int i = tid; i < Nm1; i += 256) row[i] -= lse;
}

// ---------------------------------------------------------------------------
extern "C" void kernel_launch(void* const* d_in, const int* in_sizes, int n_in,
                              void* d_out, int out_size)
{
    const float* x    = (const float*)d_in[0];
    const int*   pidx = (const int*)  d_in[1];
    const float* W1   = (const float*)d_in[2];
    const float* b1   = (const float*)d_in[3];
    const float* g1   = (const float*)d_in[4];
    const float* be1  = (const float*)d_in[5];
    const float* W2   = (const float*)d_in[6];
    const float* b2   = (const float*)d_in[7];
    const float* g2   = (const float*)d_in[8];
    const float* be2  = (const float*)d_in[9];
    const float* Wr1  = (const float*)d_in[10];
    const float* br1  = (const float*)d_in[11];
    const float* gr1  = (const float*)d_in[12];
    const float* ber1 = (const float*)d_in[13];
    const float* Wr2  = (const float*)d_in[14];
    const float* br2  = (const float*)d_in[15];
    float* out = (float*)d_out;

    const int nrows  = in_sizes[0] / CIN;     // B*N = 262144
    const int nedges = in_sizes[1];           // B*(N-1) = 262080
    const int B      = nrows - nedges;        // 64
    const int N      = nrows / B;             // 4096
    const int Nm1    = N - 1;

    const int smem1 = (16384 + 16384 + 2 * NWARPS * 128) * (int)sizeof(float);
    const int smem2 = (16384 + 128 + NWARPS * 128) * (int)sizeof(float);
    cudaFuncSetAttribute(k_mlp,  cudaFuncAttributeMaxDynamicSharedMemorySize, smem1);
    cudaFuncSetAttribute(k_edge, cudaFuncAttributeMaxDynamicSharedMemorySize, smem2);

    k_mlp<<<592, NTHREADS, smem1>>>(x, W1, b1, g1, be1, W2, b2, g2, be2, nrows);
    k_edge<<<1184, NTHREADS, smem2>>>(pidx, Wr1, br1, gr1, ber1, Wr2, br2,
                                      out, nedges, Nm1, N);
    k_lse<<<B, 256>>>(out, Nm1);
}

// round 2
// speedup vs baseline: 2.2270x; 2.2270x over previous
#include <cuda_runtime.h>
#include <math.h>

#define CIN   128
#define COUT  128
#define NWARPS 16
#define NTHREADS (NWARPS * 32)
#define RROWS 4   // rows per warp (register blocking)

// Scratch for h after stage 2 (needed for the irregular parent gather).
__device__ float g_H[64u * 4096u * 128u];

__device__ __forceinline__ float warp_sum(float v) {
#pragma unroll
    for (int o = 16; o; o >>= 1) v += __shfl_xor_sync(0xffffffffu, v, o);
    return v;
}

__device__ __forceinline__ float warp_max(float v) {
#pragma unroll
    for (int o = 16; o; o >>= 1) v = fmaxf(v, __shfl_xor_sync(0xffffffffu, v, o));
    return v;
}

__device__ __forceinline__ float elu1(float v) {
    return v > 0.0f ? v : expm1f(v);
}

// ---------------------------------------------------------------------------
// Kernel 1: h = elu(LN(elu(LN(x@W1 + b1)) @ W2 + b2))   -> g_H
// One warp per 4 rows. W float4 loaded once per k, reused across 4 rows:
// per k-iter: 1 LDS.128 (W) + 4 broadcast LDS (x) + 16 FFMA  -> balanced.
// ---------------------------------------------------------------------------
__global__ __launch_bounds__(NTHREADS, 1)
void k_mlp(const float* __restrict__ x,
           const float* __restrict__ W1, const float* __restrict__ b1,
           const float* __restrict__ g1, const float* __restrict__ be1,
           const float* __restrict__ W2, const float* __restrict__ b2,
           const float* __restrict__ g2, const float* __restrict__ be2,
           int nrows)
{
    extern __shared__ float sm[];
    float* W1s = sm;                        // 128*128
    float* W2s = sm + 16384;                // 128*128
    float* prm = sm + 32768;                // 6*128 params
    float* buf = prm + 6 * 128;             // NWARPS * RROWS * 128

    const int tid = threadIdx.x;
    for (int i = tid; i < 4096; i += NTHREADS) {
        ((float4*)W1s)[i] = ((const float4*)W1)[i];
        ((float4*)W2s)[i] = ((const float4*)W2)[i];
    }
    if (tid < 128) {
        prm[tid]       = b1[tid];
        prm[128 + tid] = g1[tid];
        prm[256 + tid] = be1[tid];
        prm[384 + tid] = b2[tid];
        prm[512 + tid] = g2[tid];
        prm[640 + tid] = be2[tid];
    }
    __syncthreads();

    const int warp = tid >> 5, lane = tid & 31;
    float* bw = buf + warp * (RROWS * 128);
    const int j = lane;                      // float4 column group

    const long ngroups = (long)nrows / RROWS;
    for (long g = (long)blockIdx.x * NWARPS + warp; g < ngroups;
         g += (long)gridDim.x * NWARPS) {
        const long row0 = g * RROWS;

        // load 4 rows of x into the warp's smem buffer
#pragma unroll
        for (int r = 0; r < RROWS; r++)
            ((float4*)(bw + r * 128))[j] = ((const float4*)(x + (row0 + r) * CIN))[j];
        __syncwarp();

        // ---- GEMM1: acc[r][c] = sum_k x[r][k] * W1[k][4j+c] ----
        float acc[RROWS][4];
#pragma unroll
        for (int r = 0; r < RROWS; r++)
#pragma unroll
            for (int c = 0; c < 4; c++) acc[r][c] = 0.0f;

#pragma unroll 8
        for (int k = 0; k < CIN; k++) {
            const float4 w = ((const float4*)(W1s + k * COUT))[j];
            const float xk0 = bw[k];
            const float xk1 = bw[128 + k];
            const float xk2 = bw[256 + k];
            const float xk3 = bw[384 + k];
            acc[0][0] = fmaf(xk0, w.x, acc[0][0]); acc[0][1] = fmaf(xk0, w.y, acc[0][1]);
            acc[0][2] = fmaf(xk0, w.z, acc[0][2]); acc[0][3] = fmaf(xk0, w.w, acc[0][3]);
            acc[1][0] = fmaf(xk1, w.x, acc[1][0]); acc[1][1] = fmaf(xk1, w.y, acc[1][1]);
            acc[1][2] = fmaf(xk1, w.z, acc[1][2]); acc[1][3] = fmaf(xk1, w.w, acc[1][3]);
            acc[2][0] = fmaf(xk2, w.x, acc[2][0]); acc[2][1] = fmaf(xk2, w.y, acc[2][1]);
            acc[2][2] = fmaf(xk2, w.z, acc[2][2]); acc[2][3] = fmaf(xk2, w.w, acc[2][3]);
            acc[3][0] = fmaf(xk3, w.x, acc[3][0]); acc[3][1] = fmaf(xk3, w.y, acc[3][1]);
            acc[3][2] = fmaf(xk3, w.z, acc[3][2]); acc[3][3] = fmaf(xk3, w.w, acc[3][3]);
        }
        __syncwarp();   // all lanes done reading bw before overwrite

        // ---- LN1 + ELU, write h into bw ----
#pragma unroll
        for (int r = 0; r < RROWS; r++) {
            float a0 = acc[r][0] + prm[4 * j + 0];
            float a1 = acc[r][1] + prm[4 * j + 1];
            float a2 = acc[r][2] + prm[4 * j + 2];
            float a3 = acc[r][3] + prm[4 * j + 3];
            float mu = warp_sum(a0 + a1 + a2 + a3) * (1.0f / COUT);
            a0 -= mu; a1 -= mu; a2 -= mu; a3 -= mu;
            float var = warp_sum(a0 * a0 + a1 * a1 + a2 * a2 + a3 * a3) * (1.0f / COUT);
            float rs = rsqrtf(var + 1e-5f);
            float4 h;
            h.x = elu1(a0 * rs * prm[128 + 4 * j + 0] + prm[256 + 4 * j + 0]);
            h.y = elu1(a1 * rs * prm[128 + 4 * j + 1] + prm[256 + 4 * j + 1]);
            h.z = elu1(a2 * rs * prm[128 + 4 * j + 2] + prm[256 + 4 * j + 2]);
            h.w = elu1(a3 * rs * prm[128 + 4 * j + 3] + prm[256 + 4 * j + 3]);
            ((float4*)(bw + r * 128))[j] = h;
        }
        __syncwarp();

        // ---- GEMM2 ----
#pragma unroll
        for (int r = 0; r < RROWS; r++)
#pragma unroll
            for (int c = 0; c < 4; c++) acc[r][c] = 0.0f;

#pragma unroll 8
        for (int k = 0; k < COUT; k++) {
            const float4 w = ((const float4*)(W2s + k * COUT))[j];
            const float hk0 = bw[k];
            const float hk1 = bw[128 + k];
            const float hk2 = bw[256 + k];
            const float hk3 = bw[384 + k];
            acc[0][0] = fmaf(hk0, w.x, acc[0][0]); acc[0][1] = fmaf(hk0, w.y, acc[0][1]);
            acc[0][2] = fmaf(hk0, w.z, acc[0][2]); acc[0][3] = fmaf(hk0, w.w, acc[0][3]);
            acc[1][0] = fmaf(hk1, w.x, acc[1][0]); acc[1][1] = fmaf(hk1, w.y, acc[1][1]);
            acc[1][2] = fmaf(hk1, w.z, acc[1][2]); acc[1][3] = fmaf(hk1, w.w, acc[1][3]);
            acc[2][0] = fmaf(hk2, w.x, acc[2][0]); acc[2][1] = fmaf(hk2, w.y, acc[2][1]);
            acc[2][2] = fmaf(hk2, w.z, acc[2][2]); acc[2][3] = fmaf(hk2, w.w, acc[2][3]);
            acc[3][0] = fmaf(hk3, w.x, acc[3][0]); acc[3][1] = fmaf(hk3, w.y, acc[3][1]);
            acc[3][2] = fmaf(hk3, w.z, acc[3][2]); acc[3][3] = fmaf(hk3, w.w, acc[3][3]);
        }
        __syncwarp();

        // ---- LN2 + ELU, write to g_H ----
#pragma unroll
        for (int r = 0; r < RROWS; r++) {
            float a0 = acc[r][0] + prm[384 + 4 * j + 0];
            float a1 = acc[r][1] + prm[384 + 4 * j + 1];
            float a2 = acc[r][2] + prm[384 + 4 * j + 2];
            float a3 = acc[r][3] + prm[384 + 4 * j + 3];
            float mu = warp_sum(a0 + a1 + a2 + a3) * (1.0f / COUT);
            a0 -= mu; a1 -= mu; a2 -= mu; a3 -= mu;
            float var = warp_sum(a0 * a0 + a1 * a1 + a2 * a2 + a3 * a3) * (1.0f / COUT);
            float rs = rsqrtf(var + 1e-5f);
            float4 o;
            o.x = elu1(a0 * rs * prm[512 + 4 * j + 0] + prm[640 + 4 * j + 0]);
            o.y = elu1(a1 * rs * prm[512 + 4 * j + 1] + prm[640 + 4 * j + 1]);
            o.z = elu1(a2 * rs * prm[512 + 4 * j + 2] + prm[640 + 4 * j + 2]);
            o.w = elu1(a3 * rs * prm[512 + 4 * j + 3] + prm[640 + 4 * j + 3]);
            ((float4*)(g_H + (row0 + r) * COUT))[j] = o;
        }
    }
}

// ---------------------------------------------------------------------------
// Kernel 2: per edge i: e = max(h[child], h[parent]);
//           r = elu(LN(e@Wr1 + br1)) @ Wr2 + br2  -> out[i]  (pre-logsumexp)
// 4 edges per warp with W reuse, 2 blocks/SM.
// ---------------------------------------------------------------------------
__global__ __launch_bounds__(NTHREADS, 2)
void k_edge(const int* __restrict__ pidx,
            const float* __restrict__ Wr1, const float* __restrict__ br1,
            const float* __restrict__ gr1, const float* __restrict__ ber1,
            const float* __restrict__ Wr2, const float* __restrict__ br2,
            float* __restrict__ out, int nedges, int Nm1, int N)
{
    extern __shared__ float sm[];
    float* Ws  = sm;                 // 128*128
    float* prm = sm + 16384;         // br1,gr1,ber1,Wr2 : 4*128
    float* buf = prm + 4 * 128;      // NWARPS * RROWS * 128

    const int tid = threadIdx.x;
    for (int i = tid; i < 4096; i += NTHREADS)
        ((float4*)Ws)[i] = ((const float4*)Wr1)[i];
    if (tid < 128) {
        prm[tid]       = br1[tid];
        prm[128 + tid] = gr1[tid];
        prm[256 + tid] = ber1[tid];
        prm[384 + tid] = Wr2[tid];
    }
    __syncthreads();

    const int warp = tid >> 5, lane = tid & 31;
    const int j = lane;
    float* bw = buf + warp * (RROWS * 128);
    const float4 w2v = ((const float4*)(prm + 384))[j];
    const float br2v = br2[0];

    const long ngroups = (long)nedges / RROWS;
    for (long g = (long)blockIdx.x * NWARPS + warp; g < ngroups;
         g += (long)gridDim.x * NWARPS) {
        const long e0 = g * RROWS;

        __syncwarp();   // prior-iteration reads of bw done
#pragma unroll
        for (int r = 0; r < RROWS; r++) {
            const long i = e0 + r;
            const int b = (int)(i / Nm1);
            const int n = (int)(i - (long)b * Nm1);
            const long crow = (long)b * N + n;
            const long prow = (long)pidx[i];
            const float4 c4 = ((const float4*)(g_H + crow * COUT))[j];
            const float4 p4 = ((const float4*)(g_H + prow * COUT))[j];
            float4 e4;
            e4.x = fmaxf(c4.x, p4.x);
            e4.y = fmaxf(c4.y, p4.y);
            e4.z = fmaxf(c4.z, p4.z);
            e4.w = fmaxf(c4.w, p4.w);
            ((float4*)(bw + r * 128))[j] = e4;
        }
        __syncwarp();

        float acc[RROWS][4];
#pragma unroll
        for (int r = 0; r < RROWS; r++)
#pragma unroll
            for (int c = 0; c < 4; c++) acc[r][c] = 0.0f;

#pragma unroll 8
        for (int k = 0; k < COUT; k++) {
            const float4 w = ((const float4*)(Ws + k * COUT))[j];
            const float e0k = bw[k];
            const float e1k = bw[128 + k];
            const float e2k = bw[256 + k];
            const float e3k = bw[384 + k];
            acc[0][0] = fmaf(e0k, w.x, acc[0][0]); acc[0][1] = fmaf(e0k, w.y, acc[0][1]);
            acc[0][2] = fmaf(e0k, w.z, acc[0][2]); acc[0][3] = fmaf(e0k, w.w, acc[0][3]);
            acc[1][0] = fmaf(e1k, w.x, acc[1][0]); acc[1][1] = fmaf(e1k, w.y, acc[1][1]);
            acc[1][2] = fmaf(e1k, w.z, acc[1][2]); acc[1][3] = fmaf(e1k, w.w, acc[1][3]);
            acc[2][0] = fmaf(e2k, w.x, acc[2][0]); acc[2][1] = fmaf(e2k, w.y, acc[2][1]);
            acc[2][2] = fmaf(e2k, w.z, acc[2][2]); acc[2][3] = fmaf(e2k, w.w, acc[2][3]);
            acc[3][0] = fmaf(e3k, w.x, acc[3][0]); acc[3][1] = fmaf(e3k, w.y, acc[3][1]);
            acc[3][2] = fmaf(e3k, w.z, acc[3][2]); acc[3][3] = fmaf(e3k, w.w, acc[3][3]);
        }

#pragma unroll
        for (int r = 0; r < RROWS; r++) {
            float a0 = acc[r][0] + prm[4 * j + 0];
            float a1 = acc[r][1] + prm[4 * j + 1];
            float a2 = acc[r][2] + prm[4 * j + 2];
            float a3 = acc[r][3] + prm[4 * j + 3];
            float mu = warp_sum(a0 + a1 + a2 + a3) * (1.0f / COUT);
            a0 -= mu; a1 -= mu; a2 -= mu; a3 -= mu;
            float var = warp_sum(a0 * a0 + a1 * a1 + a2 * a2 + a3 * a3) * (1.0f / COUT);
            const float rs = rsqrtf(var + 1e-5f);

            const float y0 = elu1(a0 * rs * prm[128 + 4 * j + 0] + prm[256 + 4 * j + 0]);
            const float y1 = elu1(a1 * rs * prm[128 + 4 * j + 1] + prm[256 + 4 * j + 1]);
            const float y2 = elu1(a2 * rs * prm[128 + 4 * j + 2] + prm[256 + 4 * j + 2]);
            const float y3 = elu1(a3 * rs * prm[128 + 4 * j + 3] + prm[256 + 4 * j + 3]);

            const float rsum = warp_sum(fmaf(y0, w2v.x,
                                        fmaf(y1, w2v.y,
                                        fmaf(y2, w2v.z, y3 * w2v.w))));
            if (lane == 0) out[e0 + r] = rsum + br2v;
        }
    }
}

// ---------------------------------------------------------------------------
// Kernel 3: per batch row, out -= logsumexp(out)
// ---------------------------------------------------------------------------
__global__ __launch_bounds__(256)
void k_lse(float* __restrict__ out, int Nm1)
{
    __shared__ float red[8];
    __shared__ float bc;
    const int b = blockIdx.x;
    float* row = out + (long)b * Nm1;
    const int tid = threadIdx.x;

    float m = -3.4e38f;
    for (int i = tid; i < Nm1; i += 256) m = fmaxf(m, row[i]);
    m = warp_max(m);
    if ((tid & 31) == 0) red[tid >> 5] = m;
    __syncthreads();
    if (tid < 32) {
        float v = (tid < 8) ? red[tid] : -3.4e38f;
        v = warp_max(v);
        if (tid == 0) bc = v;
    }
    __syncthreads();
    const float M = bc;

    float s = 0.0f;
    for (int i = tid; i < Nm1; i += 256) s += expf(row[i] - M);
    s = warp_sum(s);
    __syncthreads();
    if ((tid & 31) == 0) red[tid >> 5] = s;
    __syncthreads();
    if (tid < 32) {
        float v = (tid < 8) ? red[tid] : 0.0f;
        v = warp_sum(v);
        if (tid == 0) bc = M + logf(v);
    }
    __syncthreads();
    const float lse = bc;
    for (int i = tid; i < Nm1; i += 256) row[i] -= lse;
}

// ---------------------------------------------------------------------------
extern "C" void kernel_launch(void* const* d_in, const int* in_sizes, int n_in,
                              void* d_out, int out_size)
{
    const float* x    = (const float*)d_in[0];
    const int*   pidx = (const int*)  d_in[1];
    const float* W1   = (const float*)d_in[2];
    const float* b1   = (const float*)d_in[3];
    const float* g1   = (const float*)d_in[4];
    const float* be1  = (const float*)d_in[5];
    const float* W2   = (const float*)d_in[6];
    const float* b2   = (const float*)d_in[7];
    const float* g2   = (const float*)d_in[8];
    const float* be2  = (const float*)d_in[9];
    const float* Wr1  = (const float*)d_in[10];
    const float* br1  = (const float*)d_in[11];
    const float* gr1  = (const float*)d_in[12];
    const float* ber1 = (const float*)d_in[13];
    const float* Wr2  = (const float*)d_in[14];
    const float* br2  = (const float*)d_in[15];
    float* out = (float*)d_out;

    const int nrows  = in_sizes[0] / CIN;     // B*N = 262144
    const int nedges = in_sizes[1];           // B*(N-1) = 262080
    const int B      = nrows - nedges;        // 64
    const int N      = nrows / B;             // 4096
    const int Nm1    = N - 1;

    const int smem1 = (16384 + 16384 + 6 * 128 + NWARPS * RROWS * 128) * (int)sizeof(float);
    const int smem2 = (16384 + 4 * 128 + NWARPS * RROWS * 128) * (int)sizeof(float);
    cudaFuncSetAttribute(k_mlp,  cudaFuncAttributeMaxDynamicSharedMemorySize, smem1);
    cudaFuncSetAttribute(k_edge, cudaFuncAttributeMaxDynamicSharedMemorySize, smem2);

    k_mlp<<<592, NTHREADS, smem1>>>(x, W1, b1, g1, be1, W2, b2, g2, be2, nrows);
    k_edge<<<592, NTHREADS, smem2>>>(pidx, Wr1, br1, gr1, ber1, Wr2, br2,
                                     out, nedges, Nm1, N);
    k_lse<<<B, 256>>>(out, Nm1);
}

// round 6
// speedup vs baseline: 2.5220x; 1.1325x over previous
#include <cuda_runtime.h>
#include <cuda_bf16.h>
#include <math.h>
#include <stdint.h>

#define SA 272u   // padded smem row stride in bytes (128 bf16 + 16B pad)

// f32 h after stage 2 (needed for the irregular parent gather). 128 MiB static.
__device__ float g_H[64u * 4096u * 128u];

// ---------------------------------------------------------------------------
static __device__ __forceinline__ uint32_t s2u(const void* p) {
    uint32_t a;
    asm("{ .reg .u64 t; cvta.to.shared.u64 t, %1; cvt.u32.u64 %0, t; }" : "=r"(a) : "l"(p));
    return a;
}
static __device__ __forceinline__ void ldsm4(uint32_t& r0, uint32_t& r1, uint32_t& r2,
                                             uint32_t& r3, uint32_t addr) {
    asm volatile("ldmatrix.sync.aligned.m8n8.x4.shared.b16 {%0,%1,%2,%3}, [%4];"
                 : "=r"(r0), "=r"(r1), "=r"(r2), "=r"(r3) : "r"(addr));
}
static __device__ __forceinline__ void mma16816(float* c, const uint32_t* a,
                                                uint32_t b0, uint32_t b1) {
    asm volatile("mma.sync.aligned.m16n8k16.row.col.f32.bf16.bf16.f32 "
                 "{%0,%1,%2,%3},{%4,%5,%6,%7},{%8,%9},{%0,%1,%2,%3};"
                 : "+f"(c[0]), "+f"(c[1]), "+f"(c[2]), "+f"(c[3])
                 : "r"(a[0]), "r"(a[1]), "r"(a[2]), "r"(a[3]), "r"(b0), "r"(b1));
}
static __device__ __forceinline__ float elu1(float v) {
    return v > 0.0f ? v : expm1f(v);
}
static __device__ __forceinline__ uint32_t pack2(__nv_bfloat16 a, __nv_bfloat16 b) {
    __nv_bfloat162 t = __halves2bfloat162(a, b);
    return *(uint32_t*)&t;
}
static __device__ __forceinline__ void split2(float a, float b, uint32_t& hi, uint32_t& lo) {
    __nv_bfloat16 ha = __float2bfloat16(a), hb = __float2bfloat16(b);
    __nv_bfloat16 la = __float2bfloat16(a - __bfloat162float(ha));
    __nv_bfloat16 lb = __float2bfloat16(b - __bfloat162float(hb));
    hi = pack2(ha, hb);
    lo = pack2(la, lb);
}
__device__ __forceinline__ float warp_sum(float v) {
#pragma unroll
    for (int o = 16; o; o >>= 1) v += __shfl_xor_sync(0xffffffffu, v, o);
    return v;
}
__device__ __forceinline__ float warp_max(float v) {
#pragma unroll
    for (int o = 16; o; o >>= 1) v = fmaxf(v, __shfl_xor_sync(0xffffffffu, v, o));
    return v;
}
static __device__ __forceinline__ float qsum(float v) {
    v += __shfl_xor_sync(0xffffffffu, v, 1);
    v += __shfl_xor_sync(0xffffffffu, v, 2);
    return v;
}

// One GEMM pass over K=128: A[128x128] (row-major, stride SA) x Wt[n][k] -> c
static __device__ __forceinline__ void gemm_pass(uint32_t aBase, uint32_t wBase,
                                                 float c[2][8][4], int mrow0, int ncol0,
                                                 int lane) {
    const int arow = ((lane >> 3) & 1) * 8 + (lane & 7);
    const int acol = ((lane >> 4) & 1) * 8;
    const int brow = ((lane >> 4) & 1) * 8 + (lane & 7);
    const int bcol = ((lane >> 3) & 1) * 8;
#pragma unroll
    for (int kt = 0; kt < 8; kt++) {
        uint32_t b[8][2];
#pragma unroll
        for (int np = 0; np < 4; np++) {
            ldsm4(b[2 * np][0], b[2 * np][1], b[2 * np + 1][0], b[2 * np + 1][1],
                  wBase + (uint32_t)(ncol0 + np * 16 + brow) * SA + (kt * 16 + bcol) * 2);
        }
#pragma unroll
        for (int mt = 0; mt < 2; mt++) {
            uint32_t a[4];
            ldsm4(a[0], a[1], a[2], a[3],
                  aBase + (uint32_t)(mrow0 + mt * 16 + arow) * SA + (kt * 16 + acol) * 2);
#pragma unroll
            for (int nt = 0; nt < 8; nt++) mma16816(c[mt][nt], a, b[nt][0], b[nt][1]);
        }
    }
}

// ---------------------------------------------------------------------------
// k_mlp smem layout (bytes)
#define M_AHI 0u
#define M_ALO 34816u
#define M_W1H 69632u
#define M_W1L 104448u
#define M_W2H 139264u
#define M_W2L 174080u
#define M_PRM 208896u
#define M_RED 211968u
#define M_TOT 214016u

__global__ __launch_bounds__(256, 1)
void k_mlp(const float* __restrict__ x,
           const float* __restrict__ W1, const float* __restrict__ b1,
           const float* __restrict__ g1, const float* __restrict__ be1,
           const float* __restrict__ W2, const float* __restrict__ b2,
           const float* __restrict__ g2, const float* __restrict__ be2,
           int nrows)
{
    extern __shared__ char smem[];
    const uint32_t sb = s2u(smem);
    float* prm = (float*)(smem + M_PRM);
    float* red = (float*)(smem + M_RED);
    float* stage = (float*)smem;                 // overlaps A buffers
    const int tid = threadIdx.x, w = tid >> 5, lane = tid & 31;
    const int mrow0 = (w >> 1) * 32, half = w & 1, ncol0 = half * 64;

    // Weights: Wt[n][k] bf16 hi/lo, padded rows
    for (int idx = tid; idx < 16384; idx += 256) {
        const int k = idx >> 7, n = idx & 127;
        float wv = W1[idx];
        __nv_bfloat16 h = __float2bfloat16(wv);
        *(__nv_bfloat16*)(smem + M_W1H + n * SA + k * 2) = h;
        *(__nv_bfloat16*)(smem + M_W1L + n * SA + k * 2) = __float2bfloat16(wv - __bfloat162float(h));
        wv = W2[idx];
        h = __float2bfloat16(wv);
        *(__nv_bfloat16*)(smem + M_W2H + n * SA + k * 2) = h;
        *(__nv_bfloat16*)(smem + M_W2L + n * SA + k * 2) = __float2bfloat16(wv - __bfloat162float(h));
    }
    if (tid < 128) {
        prm[tid]       = b1[tid];
        prm[128 + tid] = g1[tid];
        prm[256 + tid] = be1[tid];
        prm[384 + tid] = b2[tid];
        prm[512 + tid] = g2[tid];
        prm[640 + tid] = be2[tid];
    }
    __syncthreads();

    const float4* x4 = (const float4*)x;
    const int ntiles = nrows >> 7;

    for (int t = blockIdx.x; t < ntiles; t += gridDim.x) {
        const long row0g = (long)t << 7;

        // ---- load x tile -> A_hi/A_lo ----
        for (int i = tid; i < 4096; i += 256) {
            const int r = i >> 5, c4 = i & 31;
            const float4 v = x4[(row0g + r) * 32 + c4];
            uint2 uh, ul;
            split2(v.x, v.y, uh.x, ul.x);
            split2(v.z, v.w, uh.y, ul.y);
            *(uint2*)(smem + M_AHI + r * SA + c4 * 8) = uh;
            *(uint2*)(smem + M_ALO + r * SA + c4 * 8) = ul;
        }
        __syncthreads();   // (1)

        // ---- GEMM1 (3-pass) ----
        float c[2][8][4];
#pragma unroll
        for (int mt = 0; mt < 2; mt++)
#pragma unroll
            for (int nt = 0; nt < 8; nt++)
#pragma unroll
                for (int e = 0; e < 4; e++) c[mt][nt][e] = 0.0f;
        gemm_pass(sb + M_AHI, sb + M_W1H, c, mrow0, ncol0, lane);
        gemm_pass(sb + M_ALO, sb + M_W1H, c, mrow0, ncol0, lane);
        gemm_pass(sb + M_AHI, sb + M_W1L, c, mrow0, ncol0, lane);

        // ---- epilogue 1: bias + LN stats ----
        {
            float s[2][2] = {{0, 0}, {0, 0}}, sq[2][2] = {{0, 0}, {0, 0}};
#pragma unroll
            for (int mt = 0; mt < 2; mt++)
#pragma unroll
                for (int nt = 0; nt < 8; nt++) {
                    const int col0 = ncol0 + nt * 8 + (lane & 3) * 2;
                    float v0 = c[mt][nt][0] + prm[col0];
                    float v1 = c[mt][nt][1] + prm[col0 + 1];
                    float v2 = c[mt][nt][2] + prm[col0];
                    float v3 = c[mt][nt][3] + prm[col0 + 1];
                    c[mt][nt][0] = v0; c[mt][nt][1] = v1;
                    c[mt][nt][2] = v2; c[mt][nt][3] = v3;
                    s[mt][0] += v0 + v1;  sq[mt][0] += v0 * v0 + v1 * v1;
                    s[mt][1] += v2 + v3;  sq[mt][1] += v2 * v2 + v3 * v3;
                }
#pragma unroll
            for (int mt = 0; mt < 2; mt++)
#pragma unroll
                for (int rh = 0; rh < 2; rh++) {
                    s[mt][rh] = qsum(s[mt][rh]);
                    sq[mt][rh] = qsum(sq[mt][rh]);
                }
            if ((lane & 3) == 0) {
#pragma unroll
                for (int mt = 0; mt < 2; mt++)
#pragma unroll
                    for (int rh = 0; rh < 2; rh++) {
                        const int row = mrow0 + mt * 16 + rh * 8 + (lane >> 2);
                        red[row * 4 + half * 2]     = s[mt][rh];
                        red[row * 4 + half * 2 + 1] = sq[mt][rh];
                    }
            }
            __syncthreads();   // (2)
            float mu[2][2], rs[2][2];
#pragma unroll
            for (int mt = 0; mt < 2; mt++)
#pragma unroll
                for (int rh = 0; rh < 2; rh++) {
                    const int row = mrow0 + mt * 16 + rh * 8 + (lane >> 2);
                    const float ts = red[row * 4] + red[row * 4 + 2];
                    const float tq = red[row * 4 + 1] + red[row * 4 + 3];
                    const float m = ts * 0.0078125f;
                    mu[mt][rh] = m;
                    rs[mt][rh] = rsqrtf(tq * 0.0078125f - m * m + 1e-5f);
                }
            // normalize + ELU -> A_hi/A_lo
#pragma unroll
            for (int mt = 0; mt < 2; mt++)
#pragma unroll
                for (int nt = 0; nt < 8; nt++) {
                    const int col0 = ncol0 + nt * 8 + (lane & 3) * 2;
#pragma unroll
                    for (int rh = 0; rh < 2; rh++) {
                        const int row = mrow0 + mt * 16 + rh * 8 + (lane >> 2);
                        const float y0 = elu1((c[mt][nt][2 * rh]     - mu[mt][rh]) * rs[mt][rh] * prm[128 + col0]     + prm[256 + col0]);
                        const float y1 = elu1((c[mt][nt][2 * rh + 1] - mu[mt][rh]) * rs[mt][rh] * prm[128 + col0 + 1] + prm[256 + col0 + 1]);
                        uint32_t hh, ll;
                        split2(y0, y1, hh, ll);
                        *(uint32_t*)(smem + M_AHI + row * SA + col0 * 2) = hh;
                        *(uint32_t*)(smem + M_ALO + row * SA + col0 * 2) = ll;
                    }
                }
        }
        __syncthreads();   // (3)

        // ---- GEMM2 (3-pass) ----
#pragma unroll
        for (int mt = 0; mt < 2; mt++)
#pragma unroll
            for (int nt = 0; nt < 8; nt++)
#pragma unroll
                for (int e = 0; e < 4; e++) c[mt][nt][e] = 0.0f;
        gemm_pass(sb + M_AHI, sb + M_W2H, c, mrow0, ncol0, lane);
        gemm_pass(sb + M_ALO, sb + M_W2H, c, mrow0, ncol0, lane);
        gemm_pass(sb + M_AHI, sb + M_W2L, c, mrow0, ncol0, lane);

        // ---- epilogue 2 ----
        {
            float s[2][2] = {{0, 0}, {0, 0}}, sq[2][2] = {{0, 0}, {0, 0}};
#pragma unroll
            for (int mt = 0; mt < 2; mt++)
#pragma unroll
                for (int nt = 0; nt < 8; nt++) {
                    const int col0 = ncol0 + nt * 8 + (lane & 3) * 2;
                    float v0 = c[mt][nt][0] + prm[384 + col0];
                    float v1 = c[mt][nt][1] + prm[384 + col0 + 1];
                    float v2 = c[mt][nt][2] + prm[384 + col0];
                    float v3 = c[mt][nt][3] + prm[384 + col0 + 1];
                    c[mt][nt][0] = v0; c[mt][nt][1] = v1;
                    c[mt][nt][2] = v2; c[mt][nt][3] = v3;
                    s[mt][0] += v0 + v1;  sq[mt][0] += v0 * v0 + v1 * v1;
                    s[mt][1] += v2 + v3;  sq[mt][1] += v2 * v2 + v3 * v3;
                }
#pragma unroll
            for (int mt = 0; mt < 2; mt++)
#pragma unroll
                for (int rh = 0; rh < 2; rh++) {
                    s[mt][rh] = qsum(s[mt][rh]);
                    sq[mt][rh] = qsum(sq[mt][rh]);
                }
            if ((lane & 3) == 0) {
#pragma unroll
                for (int mt = 0; mt < 2; mt++)
#pragma unroll
                    for (int rh = 0; rh < 2; rh++) {
                        const int row = mrow0 + mt * 16 + rh * 8 + (lane >> 2);
                        red[row * 4 + half * 2]     = s[mt][rh];
                        red[row * 4 + half * 2 + 1] = sq[mt][rh];
                    }
            }
            __syncthreads();   // (4)
#pragma unroll
            for (int mt = 0; mt < 2; mt++)
#pragma unroll
                for (int rh = 0; rh < 2; rh++) {
                    const int row = mrow0 + mt * 16 + rh * 8 + (lane >> 2);
                    const float ts = red[row * 4] + red[row * 4 + 2];
                    const float tq = red[row * 4 + 1] + red[row * 4 + 3];
                    const float m = ts * 0.0078125f;
                    const float r = rsqrtf(tq * 0.0078125f - m * m + 1e-5f);
#pragma unroll
                    for (int nt = 0; nt < 8; nt++) {
                        const int col0 = ncol0 + nt * 8 + (lane & 3) * 2;
                        const float o0 = elu1((c[mt][nt][2 * rh]     - m) * r * prm[512 + col0]     + prm[640 + col0]);
                        const float o1 = elu1((c[mt][nt][2 * rh + 1] - m) * r * prm[512 + col0 + 1] + prm[640 + col0 + 1]);
                        *(float2*)(stage + row * 132 + col0) = make_float2(o0, o1);
                    }
                }
        }
        __syncthreads();   // (5)
        {
            const int row = tid >> 1, hsel = tid & 1;
            const float4* srow = (const float4*)(stage + row * 132 + hsel * 64);
            float4* drow = (float4*)(g_H + (row0g + row) * 128 + hsel * 64);
#pragma unroll
            for (int q = 0; q < 16; q++) drow[q] = srow[q];
        }
        __syncthreads();   // (6)
    }
}

// ---------------------------------------------------------------------------
// k_edge smem layout
#define E_AHI 0u
#define E_ALO 34816u
#define E_WH  69632u
#define E_WL  104448u
#define E_PRM 139264u
#define E_RED 141312u
#define E_RDD 143360u
#define E_TOT 144384u

__global__ __launch_bounds__(256, 1)
void k_edge(const int* __restrict__ pidx,
            const float* __restrict__ Wr1, const float* __restrict__ br1,
            const float* __restrict__ gr1, const float* __restrict__ ber1,
            const float* __restrict__ Wr2, const float* __restrict__ br2,
            float* __restrict__ out, int nedges, int Nm1, int N)
{
    extern __shared__ char smem[];
    const uint32_t sb = s2u(smem);
    float* prm = (float*)(smem + E_PRM);
    float* red = (float*)(smem + E_RED);
    float* rdd = (float*)(smem + E_RDD);
    const int tid = threadIdx.x, w = tid >> 5, lane = tid & 31;
    const int mrow0 = (w >> 1) * 32, half = w & 1, ncol0 = half * 64;

    for (int idx = tid; idx < 16384; idx += 256) {
        const int k = idx >> 7, n = idx & 127;
        const float wv = Wr1[idx];
        const __nv_bfloat16 h = __float2bfloat16(wv);
        *(__nv_bfloat16*)(smem + E_WH + n * SA + k * 2) = h;
        *(__nv_bfloat16*)(smem + E_WL + n * SA + k * 2) = __float2bfloat16(wv - __bfloat162float(h));
    }
    if (tid < 128) {
        prm[tid]       = br1[tid];
        prm[128 + tid] = gr1[tid];
        prm[256 + tid] = ber1[tid];
        prm[384 + tid] = Wr2[tid];
    }
    __syncthreads();

    const float br2v = br2[0];
    const float4* gh4 = (const float4*)g_H;
    const int ntiles = (nedges + 127) >> 7;

    for (int t = blockIdx.x; t < ntiles; t += gridDim.x) {
        const long base = (long)t << 7;

        // ---- gather + max -> A_hi/A_lo (warp w handles rows 16w..16w+15) ----
#pragma unroll 2
        for (int r16 = 0; r16 < 16; r16++) {
            const int row = w * 16 + r16;
            long i = base + row;
            if (i >= nedges) i = nedges - 1;
            const int b = (int)(i / Nm1);
            const long crow = (long)b * N + (int)(i - (long)b * Nm1);
            const long prow = (long)pidx[i];
            const float4 c4v = gh4[crow * 32 + lane];
            const float4 p4v = gh4[prow * 32 + lane];
            uint2 uh, ul;
            split2(fmaxf(c4v.x, p4v.x), fmaxf(c4v.y, p4v.y), uh.x, ul.x);
            split2(fmaxf(c4v.z, p4v.z), fmaxf(c4v.w, p4v.w), uh.y, ul.y);
            *(uint2*)(smem + E_AHI + row * SA + lane * 8) = uh;
            *(uint2*)(smem + E_ALO + row * SA + lane * 8) = ul;
        }
        __syncthreads();   // (1)

        float c[2][8][4];
#pragma unroll
        for (int mt = 0; mt < 2; mt++)
#pragma unroll
            for (int nt = 0; nt < 8; nt++)
#pragma unroll
                for (int e = 0; e < 4; e++) c[mt][nt][e] = 0.0f;
        gemm_pass(sb + E_AHI, sb + E_WH, c, mrow0, ncol0, lane);
        gemm_pass(sb + E_ALO, sb + E_WH, c, mrow0, ncol0, lane);
        gemm_pass(sb + E_AHI, sb + E_WL, c, mrow0, ncol0, lane);

        // ---- bias + LN stats ----
        float s[2][2] = {{0, 0}, {0, 0}}, sq[2][2] = {{0, 0}, {0, 0}};
#pragma unroll
        for (int mt = 0; mt < 2; mt++)
#pragma unroll
            for (int nt = 0; nt < 8; nt++) {
                const int col0 = ncol0 + nt * 8 + (lane & 3) * 2;
                float v0 = c[mt][nt][0] + prm[col0];
                float v1 = c[mt][nt][1] + prm[col0 + 1];
                float v2 = c[mt][nt][2] + prm[col0];
                float v3 = c[mt][nt][3] + prm[col0 + 1];
                c[mt][nt][0] = v0; c[mt][nt][1] = v1;
                c[mt][nt][2] = v2; c[mt][nt][3] = v3;
                s[mt][0] += v0 + v1;  sq[mt][0] += v0 * v0 + v1 * v1;
                s[mt][1] += v2 + v3;  sq[mt][1] += v2 * v2 + v3 * v3;
            }
#pragma unroll
        for (int mt = 0; mt < 2; mt++)
#pragma unroll
            for (int rh = 0; rh < 2; rh++) {
                s[mt][rh] = qsum(s[mt][rh]);
                sq[mt][rh] = qsum(sq[mt][rh]);
            }
        if ((lane & 3) == 0) {
#pragma unroll
            for (int mt = 0; mt < 2; mt++)
#pragma unroll
                for (int rh = 0; rh < 2; rh++) {
                    const int row = mrow0 + mt * 16 + rh * 8 + (lane >> 2);
                    red[row * 4 + half * 2]     = s[mt][rh];
                    red[row * 4 + half * 2 + 1] = sq[mt][rh];
                }
        }
        __syncthreads();   // (2)

        // ---- normalize + ELU + dot(Wr2) ----
        float dacc[2][2] = {{0, 0}, {0, 0}};
#pragma unroll
        for (int mt = 0; mt < 2; mt++)
#pragma unroll
            for (int rh = 0; rh < 2; rh++) {
                const int row = mrow0 + mt * 16 + rh * 8 + (lane >> 2);
                const float ts = red[row * 4] + red[row * 4 + 2];
                const float tq = red[row * 4 + 1] + red[row * 4 + 3];
                const float m = ts * 0.0078125f;
                const float r = rsqrtf(tq * 0.0078125f - m * m + 1e-5f);
#pragma unroll
                for (int nt = 0; nt < 8; nt++) {
                    const int col0 = ncol0 + nt * 8 + (lane & 3) * 2;
                    const float y0 = elu1((c[mt][nt][2 * rh]     - m) * r * prm[128 + col0]     + prm[256 + col0]);
                    const float y1 = elu1((c[mt][nt][2 * rh + 1] - m) * r * prm[128 + col0 + 1] + prm[256 + col0 + 1]);
                    dacc[mt][rh] = fmaf(y0, prm[384 + col0], fmaf(y1, prm[384 + col0 + 1], dacc[mt][rh]));
                }
            }
#pragma unroll
        for (int mt = 0; mt < 2; mt++)
#pragma unroll
            for (int rh = 0; rh < 2; rh++) dacc[mt][rh] = qsum(dacc[mt][rh]);
        if ((lane & 3) == 0) {
#pragma unroll
            for (int mt = 0; mt < 2; mt++)
#pragma unroll
                for (int rh = 0; rh < 2; rh++) {
                    const int row = mrow0 + mt * 16 + rh * 8 + (lane >> 2);
                    rdd[row * 2 + half] = dacc[mt][rh];
                }
        }
        __syncthreads();   // (3)
        if (tid < 128) {
            const long i = base + tid;
            if (i < nedges) out[i] = rdd[tid * 2] + rdd[tid * 2 + 1] + br2v;
        }
    }
}

// ---------------------------------------------------------------------------
__global__ __launch_bounds__(256)
void k_lse(float* __restrict__ out, int Nm1)
{
    __shared__ float red[8];
    __shared__ float bc;
    const int b = blockIdx.x;
    float* row = out + (long)b * Nm1;
    const int tid = threadIdx.x;

    float m = -3.4e38f;
    for (int i = tid; i < Nm1; i += 256) m = fmaxf(m, row[i]);
    m = warp_max(m);
    if ((tid & 31) == 0) red[tid >> 5] = m;
    __syncthreads();
    if (tid < 32) {
        float v = (tid < 8) ? red[tid] : -3.4e38f;
        v = warp_max(v);
        if (tid == 0) bc = v;
    }
    __syncthreads();
    const float M = bc;

    float s = 0.0f;
    for (int i = tid; i < Nm1; i += 256) s += expf(row[i] - M);
    s = warp_sum(s);
    __syncthreads();
    if ((tid & 31) == 0) red[tid >> 5] = s;
    __syncthreads();
    if (tid < 32) {
        float v = (tid < 8) ? red[tid] : 0.0f;
        v = warp_sum(v);
        if (tid == 0) bc = M + logf(v);
    }
    __syncthreads();
    const float lse = bc;
    for (int i = tid; i < Nm1; i += 256) row[i] -= lse;
}

// ---------------------------------------------------------------------------
extern "C" void kernel_launch(void* const* d_in, const int* in_sizes, int n_in,
                              void* d_out, int out_size)
{
    const float* x    = (const float*)d_in[0];
    const int*   pidx = (const int*)  d_in[1];
    const float* W1   = (const float*)d_in[2];
    const float* b1   = (const float*)d_in[3];
    const float* g1   = (const float*)d_in[4];
    const float* be1  = (const float*)d_in[5];
    const float* W2   = (const float*)d_in[6];
    const float* b2   = (const float*)d_in[7];
    const float* g2   = (const float*)d_in[8];
    const float* be2  = (const float*)d_in[9];
    const float* Wr1  = (const float*)d_in[10];
    const float* br1  = (const float*)d_in[11];
    const float* gr1  = (const float*)d_in[12];
    const float* ber1 = (const float*)d_in[13];
    const float* Wr2  = (const float*)d_in[14];
    const float* br2  = (const float*)d_in[15];
    float* out = (float*)d_out;

    const int nrows  = in_sizes[0] / 128;     // B*N
    const int nedges = in_sizes[1];           // B*(N-1)
    const int B      = nrows - nedges;
    const int N      = nrows / B;
    const int Nm1    = N - 1;

    cudaFuncSetAttribute(k_mlp,  cudaFuncAttributeMaxDynamicSharedMemorySize, M_TOT);
    cudaFuncSetAttribute(k_edge, cudaFuncAttributeMaxDynamicSharedMemorySize, E_TOT);

    k_mlp<<<152, 256, M_TOT>>>(x, W1, b1, g1, be1, W2, b2, g2, be2, nrows);
    k_edge<<<152, 256, E_TOT>>>(pidx, Wr1, br1, gr1, ber1, Wr2, br2,
                                out, nedges, Nm1, N);
    k_lse<<<B, 256>>>(out, Nm1);
}

// round 9
// speedup vs baseline: 3.0019x; 1.1903x over previous
#include <cuda_runtime.h>
#include <cuda_bf16.h>
#include <math.h>
#include <stdint.h>

#define SA 272u   // padded smem row stride in bytes (128 bf16 + 16B pad)
#define NT 512    // threads per CTA (16 warps)

// f32 h after stage 2 (needed for the irregular parent gather). 128 MiB static.
__device__ float g_H[64u * 4096u * 128u];

// ---------------------------------------------------------------------------
static __device__ __forceinline__ uint32_t s2u(const void* p) {
    uint32_t a;
    asm("{ .reg .u64 t; cvta.to.shared.u64 t, %1; cvt.u32.u64 %0, t; }" : "=r"(a) : "l"(p));
    return a;
}
static __device__ __forceinline__ void ldsm4(uint32_t& r0, uint32_t& r1, uint32_t& r2,
                                             uint32_t& r3, uint32_t addr) {
    asm volatile("ldmatrix.sync.aligned.m8n8.x4.shared.b16 {%0,%1,%2,%3}, [%4];"
                 : "=r"(r0), "=r"(r1), "=r"(r2), "=r"(r3) : "r"(addr));
}
static __device__ __forceinline__ void mma16816(float* c, const uint32_t* a,
                                                uint32_t b0, uint32_t b1) {
    asm volatile("mma.sync.aligned.m16n8k16.row.col.f32.bf16.bf16.f32 "
                 "{%0,%1,%2,%3},{%4,%5,%6,%7},{%8,%9},{%0,%1,%2,%3};"
                 : "+f"(c[0]), "+f"(c[1]), "+f"(c[2]), "+f"(c[3])
                 : "r"(a[0]), "r"(a[1]), "r"(a[2]), "r"(a[3]), "r"(b0), "r"(b1));
}
static __device__ __forceinline__ float elu1(float v) {
    return v > 0.0f ? v : expm1f(v);
}
static __device__ __forceinline__ uint32_t pack2(__nv_bfloat16 a, __nv_bfloat16 b) {
    __nv_bfloat162 t = __halves2bfloat162(a, b);
    return *(uint32_t*)&t;
}
static __device__ __forceinline__ void split2(float a, float b, uint32_t& hi, uint32_t& lo) {
    __nv_bfloat16 ha = __float2bfloat16(a), hb = __float2bfloat16(b);
    __nv_bfloat16 la = __float2bfloat16(a - __bfloat162float(ha));
    __nv_bfloat16 lb = __float2bfloat16(b - __bfloat162float(hb));
    hi = pack2(ha, hb);
    lo = pack2(la, lb);
}
__device__ __forceinline__ float warp_sum(float v) {
#pragma unroll
    for (int o = 16; o; o >>= 1) v += __shfl_xor_sync(0xffffffffu, v, o);
    return v;
}
__device__ __forceinline__ float warp_max(float v) {
#pragma unroll
    for (int o = 16; o; o >>= 1) v = fmaxf(v, __shfl_xor_sync(0xffffffffu, v, o));
    return v;
}
static __device__ __forceinline__ float qsum(float v) {
    v += __shfl_xor_sync(0xffffffffu, v, 1);
    v += __shfl_xor_sync(0xffffffffu, v, 2);
    return v;
}

// One GEMM pass over K=128. Warp computes rows [mrow0,mrow0+32) x cols [ncol0,ncol0+32).
static __device__ __forceinline__ void gemm_pass(uint32_t aBase, uint32_t wBase,
                                                 float c[2][4][4], int mrow0, int ncol0,
                                                 int lane) {
    const int arow = ((lane >> 3) & 1) * 8 + (lane & 7);
    const int acol = ((lane >> 4) & 1) * 8;
    const int brow = ((lane >> 4) & 1) * 8 + (lane & 7);
    const int bcol = ((lane >> 3) & 1) * 8;
#pragma unroll
    for (int kt = 0; kt < 8; kt++) {
        uint32_t b[4][2];
#pragma unroll
        for (int np = 0; np < 2; np++) {
            ldsm4(b[2 * np][0], b[2 * np][1], b[2 * np + 1][0], b[2 * np + 1][1],
                  wBase + (uint32_t)(ncol0 + np * 16 + brow) * SA + (kt * 16 + bcol) * 2);
        }
#pragma unroll
        for (int mt = 0; mt < 2; mt++) {
            uint32_t a[4];
            ldsm4(a[0], a[1], a[2], a[3],
                  aBase + (uint32_t)(mrow0 + mt * 16 + arow) * SA + (kt * 16 + acol) * 2);
#pragma unroll
            for (int nt = 0; nt < 4; nt++) mma16816(c[mt][nt], a, b[nt][0], b[nt][1]);
        }
    }
}

// ---------------------------------------------------------------------------
// k_mlp smem layout (bytes)
#define M_AHI 0u
#define M_ALO 34816u
#define M_W1H 69632u
#define M_W1L 104448u
#define M_W2H 139264u
#define M_W2L 174080u
#define M_PRM 208896u
#define M_RED 211968u
#define M_TOT 216064u

__global__ __launch_bounds__(NT, 1)
void k_mlp(const float* __restrict__ x,
           const float* __restrict__ W1, const float* __restrict__ b1,
           const float* __restrict__ g1, const float* __restrict__ be1,
           const float* __restrict__ W2, const float* __restrict__ b2,
           const float* __restrict__ g2, const float* __restrict__ be2,
           int nrows)
{
    extern __shared__ char smem[];
    const uint32_t sb = s2u(smem);
    float* prm = (float*)(smem + M_PRM);
    float* red = (float*)(smem + M_RED);
    float* stage = (float*)smem;                 // overlaps A buffers
    const int tid = threadIdx.x, w = tid >> 5, lane = tid & 31;
    const int mrow0 = (w >> 2) * 32, quar = w & 3, ncol0 = quar * 32;

    // Weights: Wt[n][k] bf16 hi/lo, padded rows
    for (int idx = tid; idx < 16384; idx += NT) {
        const int k = idx >> 7, n = idx & 127;
        float wv = W1[idx];
        __nv_bfloat16 h = __float2bfloat16(wv);
        *(__nv_bfloat16*)(smem + M_W1H + n * SA + k * 2) = h;
        *(__nv_bfloat16*)(smem + M_W1L + n * SA + k * 2) = __float2bfloat16(wv - __bfloat162float(h));
        wv = W2[idx];
        h = __float2bfloat16(wv);
        *(__nv_bfloat16*)(smem + M_W2H + n * SA + k * 2) = h;
        *(__nv_bfloat16*)(smem + M_W2L + n * SA + k * 2) = __float2bfloat16(wv - __bfloat162float(h));
    }
    if (tid < 128) {
        prm[tid]       = b1[tid];
        prm[128 + tid] = g1[tid];
        prm[256 + tid] = be1[tid];
        prm[384 + tid] = b2[tid];
        prm[512 + tid] = g2[tid];
        prm[640 + tid] = be2[tid];
    }
    __syncthreads();

    const float4* x4 = (const float4*)x;
    const int ntiles = nrows >> 7;

    for (int t = blockIdx.x; t < ntiles; t += gridDim.x) {
        const long row0g = (long)t << 7;

        // ---- load x tile -> A_hi/A_lo ----
        for (int i = tid; i < 4096; i += NT) {
            const int r = i >> 5, c4 = i & 31;
            const float4 v = x4[(row0g + r) * 32 + c4];
            uint2 uh, ul;
            split2(v.x, v.y, uh.x, ul.x);
            split2(v.z, v.w, uh.y, ul.y);
            *(uint2*)(smem + M_AHI + r * SA + c4 * 8) = uh;
            *(uint2*)(smem + M_ALO + r * SA + c4 * 8) = ul;
        }
        __syncthreads();   // (1)

        // ---- GEMM1 (3-pass) ----
        float c[2][4][4];
#pragma unroll
        for (int mt = 0; mt < 2; mt++)
#pragma unroll
            for (int nt = 0; nt < 4; nt++)
#pragma unroll
                for (int e = 0; e < 4; e++) c[mt][nt][e] = 0.0f;
        gemm_pass(sb + M_AHI, sb + M_W1H, c, mrow0, ncol0, lane);
        gemm_pass(sb + M_ALO, sb + M_W1H, c, mrow0, ncol0, lane);
        gemm_pass(sb + M_AHI, sb + M_W1L, c, mrow0, ncol0, lane);

        // ---- epilogue 1: bias + LN stats ----
        {
            float s[2][2] = {{0, 0}, {0, 0}}, sq[2][2] = {{0, 0}, {0, 0}};
#pragma unroll
            for (int mt = 0; mt < 2; mt++)
#pragma unroll
                for (int nt = 0; nt < 4; nt++) {
                    const int col0 = ncol0 + nt * 8 + (lane & 3) * 2;
                    float v0 = c[mt][nt][0] + prm[col0];
                    float v1 = c[mt][nt][1] + prm[col0 + 1];
                    float v2 = c[mt][nt][2] + prm[col0];
                    float v3 = c[mt][nt][3] + prm[col0 + 1];
                    c[mt][nt][0] = v0; c[mt][nt][1] = v1;
                    c[mt][nt][2] = v2; c[mt][nt][3] = v3;
                    s[mt][0] += v0 + v1;  sq[mt][0] += v0 * v0 + v1 * v1;
                    s[mt][1] += v2 + v3;  sq[mt][1] += v2 * v2 + v3 * v3;
                }
#pragma unroll
            for (int mt = 0; mt < 2; mt++)
#pragma unroll
                for (int rh = 0; rh < 2; rh++) {
                    s[mt][rh] = qsum(s[mt][rh]);
                    sq[mt][rh] = qsum(sq[mt][rh]);
                }
            if ((lane & 3) == 0) {
#pragma unroll
                for (int mt = 0; mt < 2; mt++)
#pragma unroll
                    for (int rh = 0; rh < 2; rh++) {
                        const int row = mrow0 + mt * 16 + rh * 8 + (lane >> 2);
                        red[row * 8 + quar * 2]     = s[mt][rh];
                        red[row * 8 + quar * 2 + 1] = sq[mt][rh];
                    }
            }
            __syncthreads();   // (2)
            float mu[2][2], rs[2][2];
#pragma unroll
            for (int mt = 0; mt < 2; mt++)
#pragma unroll
                for (int rh = 0; rh < 2; rh++) {
                    const int row = mrow0 + mt * 16 + rh * 8 + (lane >> 2);
                    const float ts = red[row * 8] + red[row * 8 + 2] + red[row * 8 + 4] + red[row * 8 + 6];
                    const float tq = red[row * 8 + 1] + red[row * 8 + 3] + red[row * 8 + 5] + red[row * 8 + 7];
                    const float m = ts * 0.0078125f;
                    mu[mt][rh] = m;
                    rs[mt][rh] = rsqrtf(tq * 0.0078125f - m * m + 1e-5f);
                }
            // normalize + ELU -> A_hi/A_lo
#pragma unroll
            for (int mt = 0; mt < 2; mt++)
#pragma unroll
                for (int nt = 0; nt < 4; nt++) {
                    const int col0 = ncol0 + nt * 8 + (lane & 3) * 2;
#pragma unroll
                    for (int rh = 0; rh < 2; rh++) {
                        const int row = mrow0 + mt * 16 + rh * 8 + (lane >> 2);
                        const float y0 = elu1((c[mt][nt][2 * rh]     - mu[mt][rh]) * rs[mt][rh] * prm[128 + col0]     + prm[256 + col0]);
                        const float y1 = elu1((c[mt][nt][2 * rh + 1] - mu[mt][rh]) * rs[mt][rh] * prm[128 + col0 + 1] + prm[256 + col0 + 1]);
                        uint32_t hh, ll;
                        split2(y0, y1, hh, ll);
                        *(uint32_t*)(smem + M_AHI + row * SA + col0 * 2) = hh;
                        *(uint32_t*)(smem + M_ALO + row * SA + col0 * 2) = ll;
                    }
                }
        }
        __syncthreads();   // (3)

        // ---- GEMM2 (3-pass) ----
#pragma unroll
        for (int mt = 0; mt < 2; mt++)
#pragma unroll
            for (int nt = 0; nt < 4; nt++)
#pragma unroll
                for (int e = 0; e < 4; e++) c[mt][nt][e] = 0.0f;
        gemm_pass(sb + M_AHI, sb + M_W2H, c, mrow0, ncol0, lane);
        gemm_pass(sb + M_ALO, sb + M_W2H, c, mrow0, ncol0, lane);
        gemm_pass(sb + M_AHI, sb + M_W2L, c, mrow0, ncol0, lane);

        // ---- epilogue 2 ----
        {
            float s[2][2] = {{0, 0}, {0, 0}}, sq[2][2] = {{0, 0}, {0, 0}};
#pragma unroll
            for (int mt = 0; mt < 2; mt++)
#pragma unroll
                for (int nt = 0; nt < 4; nt++) {
                    const int col0 = ncol0 + nt * 8 + (lane & 3) * 2;
                    float v0 = c[mt][nt][0] + prm[384 + col0];
                    float v1 = c[mt][nt][1] + prm[384 + col0 + 1];
                    float v2 = c[mt][nt][2] + prm[384 + col0];
                    float v3 = c[mt][nt][3] + prm[384 + col0 + 1];
                    c[mt][nt][0] = v0; c[mt][nt][1] = v1;
                    c[mt][nt][2] = v2; c[mt][nt][3] = v3;
                    s[mt][0] += v0 + v1;  sq[mt][0] += v0 * v0 + v1 * v1;
                    s[mt][1] += v2 + v3;  sq[mt][1] += v2 * v2 + v3 * v3;
                }
#pragma unroll
            for (int mt = 0; mt < 2; mt++)
#pragma unroll
                for (int rh = 0; rh < 2; rh++) {
                    s[mt][rh] = qsum(s[mt][rh]);
                    sq[mt][rh] = qsum(sq[mt][rh]);
                }
            if ((lane & 3) == 0) {
#pragma unroll
                for (int mt = 0; mt < 2; mt++)
#pragma unroll
                    for (int rh = 0; rh < 2; rh++) {
                        const int row = mrow0 + mt * 16 + rh * 8 + (lane >> 2);
                        red[row * 8 + quar * 2]     = s[mt][rh];
                        red[row * 8 + quar * 2 + 1] = sq[mt][rh];
                    }
            }
            __syncthreads();   // (4)
#pragma unroll
            for (int mt = 0; mt < 2; mt++)
#pragma unroll
                for (int rh = 0; rh < 2; rh++) {
                    const int row = mrow0 + mt * 16 + rh * 8 + (lane >> 2);
                    const float ts = red[row * 8] + red[row * 8 + 2] + red[row * 8 + 4] + red[row * 8 + 6];
                    const float tq = red[row * 8 + 1] + red[row * 8 + 3] + red[row * 8 + 5] + red[row * 8 + 7];
                    const float m = ts * 0.0078125f;
                    const float r = rsqrtf(tq * 0.0078125f - m * m + 1e-5f);
#pragma unroll
                    for (int nt = 0; nt < 4; nt++) {
                        const int col0 = ncol0 + nt * 8 + (lane & 3) * 2;
                        const float o0 = elu1((c[mt][nt][2 * rh]     - m) * r * prm[512 + col0]     + prm[640 + col0]);
                        const float o1 = elu1((c[mt][nt][2 * rh + 1] - m) * r * prm[512 + col0 + 1] + prm[640 + col0 + 1]);
                        *(float2*)(stage + row * 132 + col0) = make_float2(o0, o1);
                    }
                }
        }
        __syncthreads();   // (5)
        {
            const int row = tid >> 2, qsel = tid & 3;
            const float4* srow = (const float4*)(stage + row * 132 + qsel * 32);
            float4* drow = (float4*)(g_H + (row0g + row) * 128 + qsel * 32);
#pragma unroll
            for (int q = 0; q < 8; q++) drow[q] = srow[q];
        }
        __syncthreads();   // (6)
    }
}

// ---------------------------------------------------------------------------
// k_edge smem layout
#define E_AHI 0u
#define E_ALO 34816u
#define E_WH  69632u
#define E_WL  104448u
#define E_PRM 139264u
#define E_RED 141312u
#define E_RDD 145408u
#define E_TOT 147456u

__global__ __launch_bounds__(NT, 1)
void k_edge(const int* __restrict__ pidx,
            const float* __restrict__ Wr1, const float* __restrict__ br1,
            const float* __restrict__ gr1, const float* __restrict__ ber1,
            const float* __restrict__ Wr2, const float* __restrict__ br2,
            float* __restrict__ out, int nedges, int Nm1, int N)
{
    extern __shared__ char smem[];
    const uint32_t sb = s2u(smem);
    float* prm = (float*)(smem + E_PRM);
    float* red = (float*)(smem + E_RED);
    float* rdd = (float*)(smem + E_RDD);
    const int tid = threadIdx.x, w = tid >> 5, lane = tid & 31;
    const int mrow0 = (w >> 2) * 32, quar = w & 3, ncol0 = quar * 32;

    for (int idx = tid; idx < 16384; idx += NT) {
        const int k = idx >> 7, n = idx & 127;
        const float wv = Wr1[idx];
        const __nv_bfloat16 h = __float2bfloat16(wv);
        *(__nv_bfloat16*)(smem + E_WH + n * SA + k * 2) = h;
        *(__nv_bfloat16*)(smem + E_WL + n * SA + k * 2) = __float2bfloat16(wv - __bfloat162float(h));
    }
    if (tid < 128) {
        prm[tid]       = br1[tid];
        prm[128 + tid] = gr1[tid];
        prm[256 + tid] = ber1[tid];
        prm[384 + tid] = Wr2[tid];
    }
    __syncthreads();

    const float br2v = br2[0];
    const float4* gh4 = (const float4*)g_H;
    const int ntiles = (nedges + 127) >> 7;

    for (int t = blockIdx.x; t < ntiles; t += gridDim.x) {
        const long base = (long)t << 7;

        // ---- gather + max -> A_hi/A_lo (warp w handles rows 8w..8w+7) ----
#pragma unroll
        for (int r8 = 0; r8 < 8; r8++) {
            const int row = w * 8 + r8;
            long i = base + row;
            if (i >= nedges) i = nedges - 1;
            const int b = (int)(i / Nm1);
            const long crow = (long)b * N + (int)(i - (long)b * Nm1);
            const long prow = (long)pidx[i];
            const float4 c4v = gh4[crow * 32 + lane];
            const float4 p4v = gh4[prow * 32 + lane];
            uint2 uh, ul;
            split2(fmaxf(c4v.x, p4v.x), fmaxf(c4v.y, p4v.y), uh.x, ul.x);
            split2(fmaxf(c4v.z, p4v.z), fmaxf(c4v.w, p4v.w), uh.y, ul.y);
            *(uint2*)(smem + E_AHI + row * SA + lane * 8) = uh;
            *(uint2*)(smem + E_ALO + row * SA + lane * 8) = ul;
        }
        __syncthreads();   // (1)

        float c[2][4][4];
#pragma unroll
        for (int mt = 0; mt < 2; mt++)
#pragma unroll
            for (int nt = 0; nt < 4; nt++)
#pragma unroll
                for (int e = 0; e < 4; e++) c[mt][nt][e] = 0.0f;
        gemm_pass(sb + E_AHI, sb + E_WH, c, mrow0, ncol0, lane);
        gemm_pass(sb + E_ALO, sb + E_WH, c, mrow0, ncol0, lane);
        gemm_pass(sb + E_AHI, sb + E_WL, c, mrow0, ncol0, lane);

        // ---- bias + LN stats ----
        float s[2][2] = {{0, 0}, {0, 0}}, sq[2][2] = {{0, 0}, {0, 0}};
#pragma unroll
        for (int mt = 0; mt < 2; mt++)
#pragma unroll
            for (int nt = 0; nt < 4; nt++) {
                const int col0 = ncol0 + nt * 8 + (lane & 3) * 2;
                float v0 = c[mt][nt][0] + prm[col0];
                float v1 = c[mt][nt][1] + prm[col0 + 1];
                float v2 = c[mt][nt][2] + prm[col0];
                float v3 = c[mt][nt][3] + prm[col0 + 1];
                c[mt][nt][0] = v0; c[mt][nt][1] = v1;
                c[mt][nt][2] = v2; c[mt][nt][3] = v3;
                s[mt][0] += v0 + v1;  sq[mt][0] += v0 * v0 + v1 * v1;
                s[mt][1] += v2 + v3;  sq[mt][1] += v2 * v2 + v3 * v3;
            }
#pragma unroll
        for (int mt = 0; mt < 2; mt++)
#pragma unroll
            for (int rh = 0; rh < 2; rh++) {
                s[mt][rh] = qsum(s[mt][rh]);
                sq[mt][rh] = qsum(sq[mt][rh]);
            }
        if ((lane & 3) == 0) {
#pragma unroll
            for (int mt = 0; mt < 2; mt++)
#pragma unroll
                for (int rh = 0; rh < 2; rh++) {
                    const int row = mrow0 + mt * 16 + rh * 8 + (lane >> 2);
                    red[row * 8 + quar * 2]     = s[mt][rh];
                    red[row * 8 + quar * 2 + 1] = sq[mt][rh];
                }
        }
        __syncthreads();   // (2)

        // ---- normalize + ELU + dot(Wr2) ----
        float dacc[2][2] = {{0, 0}, {0, 0}};
#pragma unroll
        for (int mt = 0; mt < 2; mt++)
#pragma unroll
            for (int rh = 0; rh < 2; rh++) {
                const int row = mrow0 + mt * 16 + rh * 8 + (lane >> 2);
                const float ts = red[row * 8] + red[row * 8 + 2] + red[row * 8 + 4] + red[row * 8 + 6];
                const float tq = red[row * 8 + 1] + red[row * 8 + 3] + red[row * 8 + 5] + red[row * 8 + 7];
                const float m = ts * 0.0078125f;
                const float r = rsqrtf(tq * 0.0078125f - m * m + 1e-5f);
#pragma unroll
                for (int nt = 0; nt < 4; nt++) {
                    const int col0 = ncol0 + nt * 8 + (lane & 3) * 2;
                    const float y0 = elu1((c[mt][nt][2 * rh]     - m) * r * prm[128 + col0]     + prm[256 + col0]);
                    const float y1 = elu1((c[mt][nt][2 * rh + 1] - m) * r * prm[128 + col0 + 1] + prm[256 + col0 + 1]);
                    dacc[mt][rh] = fmaf(y0, prm[384 + col0], fmaf(y1, prm[384 + col0 + 1], dacc[mt][rh]));
                }
            }
#pragma unroll
        for (int mt = 0; mt < 2; mt++)
#pragma unroll
            for (int rh = 0; rh < 2; rh++) dacc[mt][rh] = qsum(dacc[mt][rh]);
        if ((lane & 3) == 0) {
#pragma unroll
            for (int mt = 0; mt < 2; mt++)
#pragma unroll
                for (int rh = 0; rh < 2; rh++) {
                    const int row = mrow0 + mt * 16 + rh * 8 + (lane >> 2);
                    rdd[row * 4 + quar] = dacc[mt][rh];
                }
        }
        __syncthreads();   // (3)
        if (tid < 128) {
            const long i = base + tid;
            if (i < nedges)
                out[i] = rdd[tid * 4] + rdd[tid * 4 + 1] + rdd[tid * 4 + 2] + rdd[tid * 4 + 3] + br2v;
        }
    }
}

// ---------------------------------------------------------------------------
__global__ __launch_bounds__(256)
void k_lse(float* __restrict__ out, int Nm1)
{
    __shared__ float red[8];
    __shared__ float bc;
    const int b = blockIdx.x;
    float* row = out + (long)b * Nm1;
    const int tid = threadIdx.x;

    float m = -3.4e38f;
    for (int i = tid; i < Nm1; i += 256) m = fmaxf(m, row[i]);
    m = warp_max(m);
    if ((tid & 31) == 0) red[tid >> 5] = m;
    __syncthreads();
    if (tid < 32) {
        float v = (tid < 8) ? red[tid] : -3.4e38f;
        v = warp_max(v);
        if (tid == 0) bc = v;
    }
    __syncthreads();
    const float M = bc;

    float s = 0.0f;
    for (int i = tid; i < Nm1; i += 256) s += expf(row[i] - M);
    s = warp_sum(s);
    __syncthreads();
    if ((tid & 31) == 0) red[tid >> 5] = s;
    __syncthreads();
    if (tid < 32) {
        float v = (tid < 8) ? red[tid] : 0.0f;
        v = warp_sum(v);
        if (tid == 0) bc = M + logf(v);
    }
    __syncthreads();
    const float lse = bc;
    for (int i = tid; i < Nm1; i += 256) row[i] -= lse;
}

// ---------------------------------------------------------------------------
extern "C" void kernel_launch(void* const* d_in, const int* in_sizes, int n_in,
                              void* d_out, int out_size)
{
    const float* x    = (const float*)d_in[0];
    const int*   pidx = (const int*)  d_in[1];
    const float* W1   = (const float*)d_in[2];
    const float* b1   = (const float*)d_in[3];
    const float* g1   = (const float*)d_in[4];
    const float* be1  = (const float*)d_in[5];
    const float* W2   = (const float*)d_in[6];
    const float* b2   = (const float*)d_in[7];
    const float* g2   = (const float*)d_in[8];
    const float* be2  = (const float*)d_in[9];
    const float* Wr1  = (const float*)d_in[10];
    const float* br1  = (const float*)d_in[11];
    const float* gr1  = (const float*)d_in[12];
    const float* ber1 = (const float*)d_in[13];
    const float* Wr2  = (const float*)d_in[14];
    const float* br2  = (const float*)d_in[15];
    float* out = (float*)d_out;

    const int nrows  = in_sizes[0] / 128;     // B*N
    const int nedges = in_sizes[1];           // B*(N-1)
    const int B      = nrows - nedges;
    const int N      = nrows / B;
    const int Nm1    = N - 1;

    cudaFuncSetAttribute(k_mlp,  cudaFuncAttributeMaxDynamicSharedMemorySize, M_TOT);
    cudaFuncSetAttribute(k_edge, cudaFuncAttributeMaxDynamicSharedMemorySize, E_TOT);

    k_mlp<<<152, NT, M_TOT>>>(x, W1, b1, g1, be1, W2, b2, g2, be2, nrows);
    k_edge<<<152, NT, E_TOT>>>(pidx, Wr1, br1, gr1, ber1, Wr2, br2,
                               out, nedges, Nm1, N);
    k_lse<<<B, 256>>>(out, Nm1);
}